// round 13
// baseline (speedup 1.0000x reference)
#include <cuda_runtime.h>
#include <cuda_bf16.h>
#include <cstdint>

#define NN 50000
#define NE 800000
#define DIM 256
#define RB 391   // ceil(NN/128)

typedef unsigned long long ull;

// ---------------- global scratch ----------------
__device__ __align__(16) float g_z[NN * DIM];          // z = x + aggr
__device__ __align__(128) char g_weHh[2][16384];       // We half-images [64k][128n] bf16 hi
__device__ __align__(128) char g_weLh[2][16384];
__device__ __align__(128) char g_w1H[131072];          // W1 images, 4 chunks x 32KB (swz<9>)
__device__ __align__(128) char g_w1L[131072];
__device__ __align__(128) char g_w2H[131072];
__device__ __align__(128) char g_w2L[131072];
// sorting
__device__ int g_cnt[NN + 1];
__device__ int g_woff[NN];
__device__ int g_eid_s[NE], g_src_s[NE], g_dst_s[NE];

// ---------------- helpers ----------------
template <int S>
__device__ __forceinline__ uint32_t swz(uint32_t off) {
    return off ^ (((off >> S) & 7u) << 4);
}
__device__ __forceinline__ int permp(int np) {
    return (np & ~7) | ((np & 7) >> 1) | ((np & 1) << 2);
}
__device__ __forceinline__ uint32_t smem_u32(const void* p) {
    uint32_t a;
    asm("{ .reg .u64 t; cvta.to.shared.u64 t, %1; cvt.u32.u64 %0, t; }" : "=r"(a) : "l"(p));
    return a;
}
__device__ __forceinline__ void ldsm4(uint32_t r[4], uint32_t a) {
    asm volatile("ldmatrix.sync.aligned.m8n8.x4.shared.b16 {%0,%1,%2,%3}, [%4];"
                 : "=r"(r[0]), "=r"(r[1]), "=r"(r[2]), "=r"(r[3]) : "r"(a));
}
__device__ __forceinline__ void ldsm4t(uint32_t r[4], uint32_t a) {
    asm volatile("ldmatrix.sync.aligned.m8n8.x4.trans.shared.b16 {%0,%1,%2,%3}, [%4];"
                 : "=r"(r[0]), "=r"(r[1]), "=r"(r[2]), "=r"(r[3]) : "r"(a));
}
__device__ __forceinline__ void mma16816(float d[4], const uint32_t a[4], const uint32_t b[2]) {
    asm volatile("mma.sync.aligned.m16n8k16.row.col.f32.bf16.bf16.f32 "
                 "{%0,%1,%2,%3}, {%4,%5,%6,%7}, {%8,%9}, {%0,%1,%2,%3};"
                 : "+f"(d[0]), "+f"(d[1]), "+f"(d[2]), "+f"(d[3])
                 : "r"(a[0]), "r"(a[1]), "r"(a[2]), "r"(a[3]), "r"(b[0]), "r"(b[1]));
}
__device__ __forceinline__ void red4(float* a, float4 v) {
    asm volatile("red.global.add.v4.f32 [%0], {%1,%2,%3,%4};"
                 :: "l"(a), "f"(v.x), "f"(v.y), "f"(v.z), "f"(v.w));
}
__device__ __forceinline__ void cpa16(uint32_t dst, const void* src) {
    asm volatile("cp.async.cg.shared.global [%0], [%1], 16;" :: "r"(dst), "l"(src));
}
__device__ __forceinline__ void cpa_commit() { asm volatile("cp.async.commit_group;"); }
__device__ __forceinline__ void cpa_wait0()  { asm volatile("cp.async.wait_group 0;"); }

__device__ __forceinline__ void store_pair(char* bH, char* bL, uint32_t off, float2 v) {
    __nv_bfloat16 h0 = __float2bfloat16(v.x), h1 = __float2bfloat16(v.y);
    __nv_bfloat16 l0 = __float2bfloat16(v.x - __bfloat162float(h0));
    __nv_bfloat16 l1 = __float2bfloat16(v.y - __bfloat162float(h1));
    *(__nv_bfloat162*)(bH + off) = __halves2bfloat162(h0, h1);
    *(__nv_bfloat162*)(bL + off) = __halves2bfloat162(l0, l1);
}

// ---------------------------------------------------------------------------
// mma_chunk9: A[32r x 64k] @ B[64k x 64c], B image 512B rows swz<9> (MLP)
// 3 passes: Ah*Bh + Ah*Bl + Al*Bh, B fragments register-cached.
// ---------------------------------------------------------------------------
__device__ __forceinline__ void mma_chunk9(float acc[2][8][4],
    uint32_t aH, uint32_t aL, uint32_t bH, uint32_t bL,
    int mbase, int nbase, int l)
{
    const int lr = l & 7, lg8 = ((l >> 3) & 1) * 8, lh8 = (l >> 4) * 8;
    #pragma unroll
    for (int ks = 0; ks < 4; ks++) {
        uint32_t a[2][4], bh[8][2], bl[8][2];
        #pragma unroll
        for (int mf = 0; mf < 2; mf++)
            ldsm4(a[mf], aH + swz<7>((uint32_t)((mbase + mf * 16 + lr + lg8) * 128
                                                + (ks * 16 + lh8) * 2)));
        #pragma unroll
        for (int nq = 0; nq < 4; nq++) {
            uint32_t r4[4];
            uint32_t off = swz<9>((uint32_t)((ks * 16 + lr + lg8) * 512
                                             + (nbase + nq * 16 + lh8) * 2));
            ldsm4t(r4, bH + off);
            bh[2 * nq][0] = r4[0]; bh[2 * nq][1] = r4[1];
            bh[2 * nq + 1][0] = r4[2]; bh[2 * nq + 1][1] = r4[3];
            ldsm4t(r4, bL + off);
            bl[2 * nq][0] = r4[0]; bl[2 * nq][1] = r4[1];
            bl[2 * nq + 1][0] = r4[2]; bl[2 * nq + 1][1] = r4[3];
        }
        #pragma unroll
        for (int mf = 0; mf < 2; mf++)
            #pragma unroll
            for (int nf = 0; nf < 8; nf++)
                mma16816(acc[mf][nf], a[mf], bh[nf]);
        #pragma unroll
        for (int mf = 0; mf < 2; mf++)
            #pragma unroll
            for (int nf = 0; nf < 8; nf++)
                mma16816(acc[mf][nf], a[mf], bl[nf]);
        #pragma unroll
        for (int mf = 0; mf < 2; mf++)
            ldsm4(a[mf], aL + swz<7>((uint32_t)((mbase + mf * 16 + lr + lg8) * 128
                                                + (ks * 16 + lh8) * 2)));
        #pragma unroll
        for (int mf = 0; mf < 2; mf++)
            #pragma unroll
            for (int nf = 0; nf < 8; nf++)
                mma16816(acc[mf][nf], a[mf], bh[nf]);
    }
}

// mma_chunk8: same, B half-image 256B rows swz<8> (edge kernel)
__device__ __forceinline__ void mma_chunk8(float acc[2][8][4],
    uint32_t aH, uint32_t aL, uint32_t bH, uint32_t bL,
    int mbase, int nbase, int l)
{
    const int lr = l & 7, lg8 = ((l >> 3) & 1) * 8, lh8 = (l >> 4) * 8;
    #pragma unroll
    for (int ks = 0; ks < 4; ks++) {
        uint32_t a[2][4], bh[8][2], bl[8][2];
        #pragma unroll
        for (int mf = 0; mf < 2; mf++)
            ldsm4(a[mf], aH + swz<7>((uint32_t)((mbase + mf * 16 + lr + lg8) * 128
                                                + (ks * 16 + lh8) * 2)));
        #pragma unroll
        for (int nq = 0; nq < 4; nq++) {
            uint32_t r4[4];
            uint32_t off = swz<8>((uint32_t)((ks * 16 + lr + lg8) * 256
                                             + (nbase + nq * 16 + lh8) * 2));
            ldsm4t(r4, bH + off);
            bh[2 * nq][0] = r4[0]; bh[2 * nq][1] = r4[1];
            bh[2 * nq + 1][0] = r4[2]; bh[2 * nq + 1][1] = r4[3];
            ldsm4t(r4, bL + off);
            bl[2 * nq][0] = r4[0]; bl[2 * nq][1] = r4[1];
            bl[2 * nq + 1][0] = r4[2]; bl[2 * nq + 1][1] = r4[3];
        }
        #pragma unroll
        for (int mf = 0; mf < 2; mf++)
            #pragma unroll
            for (int nf = 0; nf < 8; nf++)
                mma16816(acc[mf][nf], a[mf], bh[nf]);
        #pragma unroll
        for (int mf = 0; mf < 2; mf++)
            #pragma unroll
            for (int nf = 0; nf < 8; nf++)
                mma16816(acc[mf][nf], a[mf], bl[nf]);
        #pragma unroll
        for (int mf = 0; mf < 2; mf++)
            ldsm4(a[mf], aL + swz<7>((uint32_t)((mbase + mf * 16 + lr + lg8) * 128
                                                + (ks * 16 + lh8) * 2)));
        #pragma unroll
        for (int mf = 0; mf < 2; mf++)
            #pragma unroll
            for (int nf = 0; nf < 8; nf++)
                mma16816(acc[mf][nf], a[mf], bh[nf]);
    }
}

// ---------------------------------------------------------------------------
// sorting kernels
// ---------------------------------------------------------------------------
__global__ __launch_bounds__(256) void k_zero() {
    int i = blockIdx.x * 256 + threadIdx.x;
    if (i <= NN) g_cnt[i] = 0;
}
__global__ __launch_bounds__(256) void k_hist(const int* __restrict__ eidx) {
    int i = blockIdx.x * 256 + threadIdx.x;
    atomicAdd(&g_cnt[1 + eidx[NE + i]], 1);
}
__global__ __launch_bounds__(1024) void k_scan() {
    const int C = 49;   // 1024*49 = 50176 >= 50001
    int t = threadIdx.x;
    int base = t * C;
    int s = 0;
    for (int i = 0; i < C; i++) {
        int idx = base + i;
        if (idx <= NN) s += g_cnt[idx];
    }
    __shared__ int ps[1024];
    ps[t] = s;
    __syncthreads();
    for (int off = 1; off < 1024; off <<= 1) {
        int v = (t >= off) ? ps[t - off] : 0;
        __syncthreads();
        ps[t] += v;
        __syncthreads();
    }
    int run = ps[t] - s;   // exclusive prefix of this thread's chunk
    for (int i = 0; i < C; i++) {
        int idx = base + i;
        if (idx <= NN) {
            run += g_cnt[idx];
            g_cnt[idx] = run;
            if (idx < NN) g_woff[idx] = run;
        }
    }
}
__global__ __launch_bounds__(256) void k_scatter(const int* __restrict__ eidx) {
    int i = blockIdx.x * 256 + threadIdx.x;
    int d = eidx[NE + i];
    int p = atomicAdd(&g_woff[d], 1);
    g_eid_s[p] = i;
    g_src_s[p] = eidx[i];
    g_dst_s[p] = d;
}

// ---------------------------------------------------------------------------
// k_prep: build bf16 hi/lo weight images
// ---------------------------------------------------------------------------
__global__ __launch_bounds__(256) void k_prep(const float* __restrict__ We,
                                              const float* __restrict__ W1,
                                              const float* __restrict__ W2)
{
    int i = blockIdx.x * 256 + threadIdx.x;
    if (i < 8192) {                       // We: 64k x 128 pairs -> 2 half-images
        int k = i >> 7, np = i & 127;
        int half = np >> 6, npl = np & 63;
        uint32_t off = swz<8>((uint32_t)(k * 256 + permp(npl) * 4));
        store_pair(g_weHh[half], g_weLh[half], off, ((const float2*)We)[i]);
    } else if (i < 40960) {               // W1
        int j = i - 8192;
        int kc = j >> 13, k = (j >> 7) & 63, np = j & 127;
        uint32_t off = (uint32_t)(kc * 32768) + swz<9>((uint32_t)(k * 512 + permp(np) * 4));
        store_pair(g_w1H, g_w1L, off, ((const float2*)W1)[j]);
    } else if (i < 73728) {               // W2
        int j = i - 40960;
        int kc = j >> 13, k = (j >> 7) & 63, np = j & 127;
        uint32_t off = (uint32_t)(kc * 32768) + swz<9>((uint32_t)(k * 512 + permp(np) * 4));
        store_pair(g_w2H, g_w2L, off, ((const float2*)W2)[j]);
    }
}

// ---------------------------------------------------------------------------
// k_init: z = x
// ---------------------------------------------------------------------------
__global__ __launch_bounds__(256) void k_init(const float4* __restrict__ x) {
    int i = blockIdx.x * 256 + threadIdx.x;
    reinterpret_cast<float4*>(g_z)[i] = x[i];
}

// ---------------------------------------------------------------------------
// k_edge v3: CTA = 128 dst-SORTED edges, 256 threads (wm4 x wn2), occ 2.
// A = gathered ea rows (by sorted eid); B = We half-image (single buffer/hf).
// Epilogue: fragments + x[src] + be + relu -> scratch; segmented run-reduction
// over sorted dst emits one red4 per run.
// ---------------------------------------------------------------------------
#define E_AH  0
#define E_AL  16384
#define E_BH  32768
#define E_BL  49152
#define E_SCR 65536               // 2 slots x 128 rows x 144B = 36864
#define E_IDX 102400              // eid/src/dst, 128 ints each
#define E_SMEM 104448

__global__ __launch_bounds__(256, 2) void k_edge(
    const float* __restrict__ x, const float* __restrict__ ea,
    const float* __restrict__ be)
{
    extern __shared__ char sm[];
    const int t = threadIdx.x, w = t >> 5, l = t & 31;
    const int wm = w & 3, wn = w >> 2, j = l & 3;
    const uint32_t sb = smem_u32(sm);
    int* s_eid = (int*)(sm + E_IDX);
    int* s_src = s_eid + 128;
    int* s_dst = s_eid + 256;
    const int e0 = blockIdx.x * 128;

    if (t < 128) {
        s_eid[t] = g_eid_s[e0 + t];
        s_src[t] = g_src_s[e0 + t];
        s_dst[t] = g_dst_s[e0 + t];
    }
    __syncthreads();

    // B half 0 (16K hi + 16K lo)
    #pragma unroll
    for (int i0 = 0; i0 < 4; i0++) {
        int i = i0 * 256 + t;
        cpa16(sb + E_BH + i * 16, g_weHh[0] + i * 16);
        cpa16(sb + E_BL + i * 16, g_weLh[0] + i * 16);
    }
    cpa_commit();

    // A: gather ea rows by sorted eid, convert to bf16 hi/lo
    #pragma unroll
    for (int i0 = 0; i0 < 16; i0++) {
        int i = i0 * 256 + t;
        int r = i >> 5, kp = i & 31;
        const float2* earow = (const float2*)(ea + (size_t)s_eid[r] * 64);
        store_pair(sm + E_AH, sm + E_AL, swz<7>((uint32_t)(r * 128 + kp * 4)), earow[kp]);
    }
    cpa_wait0();
    __syncthreads();

    #pragma unroll 1
    for (int hf = 0; hf < 2; hf++) {
        float acc[2][8][4];
        #pragma unroll
        for (int mf = 0; mf < 2; mf++)
            #pragma unroll
            for (int nf = 0; nf < 8; nf++) {
                acc[mf][nf][0] = 0.f; acc[mf][nf][1] = 0.f;
                acc[mf][nf][2] = 0.f; acc[mf][nf][3] = 0.f;
            }
        mma_chunk8(acc, sb + E_AH, sb + E_AL, sb + E_BH, sb + E_BL,
                   wm * 32, wn * 64, l);
        __syncthreads();            // all warps done with this B half
        if (hf == 0) {              // overlap next-half B load with epilogue
            #pragma unroll
            for (int i0 = 0; i0 < 4; i0++) {
                int i = i0 * 256 + t;
                cpa16(sb + E_BH + i * 16, g_weHh[1] + i * 16);
                cpa16(sb + E_BL + i * 16, g_weLh[1] + i * 16);
            }
            cpa_commit();
        }

        #pragma unroll 1
        for (int it = 0; it < 2; it++) {
            // dump: relu(acc + x[src] + be) -> scratch slot wn (32 cols)
            #pragma unroll
            for (int mf = 0; mf < 2; mf++)
                #pragma unroll
                for (int rh = 0; rh < 2; rh++) {
                    int row = wm * 32 + mf * 16 + rh * 8 + (l >> 2);
                    const float* xr = x + (size_t)s_src[row] * DIM;
                    #pragma unroll
                    for (int nq2 = 0; nq2 < 2; nq2++) {
                        int nq = it * 2 + nq2;
                        int gcol = hf * 128 + wn * 64 + nq * 16 + 4 * j;
                        float4 xv = __ldg((const float4*)(xr + gcol));
                        float4 bv = __ldg((const float4*)(be + gcol));
                        float4 v;
                        v.x = fmaxf(acc[mf][2 * nq][2 * rh]     + xv.x + bv.x, 0.f);
                        v.y = fmaxf(acc[mf][2 * nq][2 * rh + 1] + xv.y + bv.y, 0.f);
                        v.z = fmaxf(acc[mf][2 * nq + 1][2 * rh]     + xv.z + bv.z, 0.f);
                        v.w = fmaxf(acc[mf][2 * nq + 1][2 * rh + 1] + xv.w + bv.w, 0.f);
                        *(float4*)(sm + E_SCR + wn * 18432 + row * 144
                                   + (nq2 * 16 + 4 * j) * 4) = v;
                    }
                }
            __syncthreads();
            // aggregate: segmented run-reduction over 8 sorted rows per thread
            {
                int slot = t >> 7;
                int lane = t & 127;
                int chunk = lane & 7;
                int blk = lane >> 3;
                int gcol = hf * 128 + slot * 64 + it * 32 + chunk * 4;
                const char* scr = sm + E_SCR + slot * 18432;
                float4 a4 = make_float4(0.f, 0.f, 0.f, 0.f);
                int dprev = -1;
                #pragma unroll
                for (int r8 = 0; r8 < 8; r8++) {
                    int row = blk * 8 + r8;
                    int d = s_dst[row];
                    float4 v = *(const float4*)(scr + row * 144 + chunk * 16);
                    if (d != dprev) {
                        if (dprev >= 0) red4(g_z + (size_t)dprev * DIM + gcol, a4);
                        a4 = v; dprev = d;
                    } else {
                        a4.x += v.x; a4.y += v.y; a4.z += v.z; a4.w += v.w;
                    }
                }
                red4(g_z + (size_t)dprev * DIM + gcol, a4);
            }
            __syncthreads();
        }
        if (hf == 0) {
            cpa_wait0();
            __syncthreads();
        }
    }
}

// ---------------------------------------------------------------------------
// k_mlp (FUSED, R11 version): layer1 -> h1 smem -> layer2 -> LayerNorm -> out
// 512 threads (wm4 x wn4), CTA = 128 rows x 256 cols.
// ---------------------------------------------------------------------------
#define P_A(buf)  ((buf) * 32768)
#define P_AL(buf) ((buf) * 32768 + 16384)
#define P_B(buf)  (65536 + (buf) * 65536)
#define P_BL(buf) (65536 + (buf) * 65536 + 32768)
#define H1(kc)    ((kc) * 32768)
#define W2HI      131072
#define W2LO      163840
#define LNPART    131072
#define P_SMEM    196608

__global__ __launch_bounds__(512, 1) void k_mlp(
    const float* __restrict__ x, const float* __restrict__ b1,
    const float* __restrict__ b2, const float* __restrict__ gamma,
    const float* __restrict__ beta, float* __restrict__ out)
{
    extern __shared__ char sm[];
    const int t = threadIdx.x, w = t >> 5, l = t & 31;
    const int wm = w & 3, wn = w >> 2, j = l & 3;
    const uint32_t sb = smem_u32(sm);
    const int rb = blockIdx.x, rowb = rb * 128;

    // ---------------- phase 1: h1pre = z @ W1 ----------------
    #pragma unroll
    for (int i0 = 0; i0 < 4; i0++) {
        int i = i0 * 512 + t;
        cpa16(sb + P_B(0) + i * 16, g_w1H + i * 16);
        cpa16(sb + P_BL(0) + i * 16, g_w1L + i * 16);
    }
    cpa_commit();
    #pragma unroll
    for (int i0 = 0; i0 < 8; i0++) {
        int i = i0 * 512 + t;
        int r = i >> 5, kp = i & 31;
        int row = min(rowb + r, NN - 1);
        float2 v = *(const float2*)(g_z + (size_t)row * DIM + kp * 2);
        store_pair(sm + P_A(0), sm + P_AL(0), swz<7>((uint32_t)(r * 128 + kp * 4)), v);
    }

    float acc[2][8][4];
    #pragma unroll
    for (int mf = 0; mf < 2; mf++)
        #pragma unroll
        for (int nf = 0; nf < 8; nf++) {
            acc[mf][nf][0] = 0.f; acc[mf][nf][1] = 0.f;
            acc[mf][nf][2] = 0.f; acc[mf][nf][3] = 0.f;
        }

    #pragma unroll 1
    for (int c = 0; c < 4; c++) {
        cpa_wait0();
        __syncthreads();
        if (c < 3) {
            int nb = (c + 1) & 1;
            #pragma unroll
            for (int i0 = 0; i0 < 4; i0++) {
                int i = i0 * 512 + t;
                cpa16(sb + P_B(nb) + i * 16, g_w1H + (c + 1) * 32768 + i * 16);
                cpa16(sb + P_BL(nb) + i * 16, g_w1L + (c + 1) * 32768 + i * 16);
            }
            cpa_commit();
            #pragma unroll
            for (int i0 = 0; i0 < 8; i0++) {
                int i = i0 * 512 + t;
                int r = i >> 5, kp = i & 31;
                int row = min(rowb + r, NN - 1);
                float2 v = *(const float2*)(g_z + (size_t)row * DIM + (c + 1) * 64 + kp * 2);
                store_pair(sm + P_A(nb), sm + P_AL(nb),
                           swz<7>((uint32_t)(r * 128 + kp * 4)), v);
            }
        }
        int cb = c & 1;
        mma_chunk9(acc, sb + P_A(cb), sb + P_AL(cb), sb + P_B(cb), sb + P_BL(cb),
                   wm * 32, wn * 64, l);
    }
    __syncthreads();

    // prefetch W2 chunk 0 (overlaps the h1 conversion)
    #pragma unroll
    for (int i0 = 0; i0 < 4; i0++) {
        int i = i0 * 512 + t;
        cpa16(sb + W2HI + i * 16, g_w2H + i * 16);
        cpa16(sb + W2LO + i * 16, g_w2L + i * 16);
    }
    cpa_commit();

    // h1 = relu(acc + b1) -> bf16 hi/lo images in smem
    #pragma unroll
    for (int mf = 0; mf < 2; mf++)
        #pragma unroll
        for (int rh = 0; rh < 2; rh++) {
            int r = wm * 32 + mf * 16 + rh * 8 + (l >> 2);
            #pragma unroll
            for (int nq = 0; nq < 4; nq++) {
                int col = wn * 64 + nq * 16 + 4 * j;
                float4 bv = __ldg((const float4*)b1 + (col >> 2));
                float h0 = fmaxf(acc[mf][2 * nq][2 * rh]     + bv.x, 0.f);
                float h1 = fmaxf(acc[mf][2 * nq][2 * rh + 1] + bv.y, 0.f);
                float h2 = fmaxf(acc[mf][2 * nq + 1][2 * rh]     + bv.z, 0.f);
                float h3 = fmaxf(acc[mf][2 * nq + 1][2 * rh + 1] + bv.w, 0.f);
                __nv_bfloat16 b0 = __float2bfloat16(h0), b1v = __float2bfloat16(h1);
                __nv_bfloat16 b2v = __float2bfloat16(h2), b3 = __float2bfloat16(h3);
                __nv_bfloat16 c0 = __float2bfloat16(h0 - __bfloat162float(b0));
                __nv_bfloat16 c1 = __float2bfloat16(h1 - __bfloat162float(b1v));
                __nv_bfloat16 c2 = __float2bfloat16(h2 - __bfloat162float(b2v));
                __nv_bfloat16 c3 = __float2bfloat16(h3 - __bfloat162float(b3));
                int kc = col >> 6, kp = col & 63;
                uint32_t off = (uint32_t)H1(kc) + swz<7>((uint32_t)(r * 128 + kp * 2));
                __nv_bfloat162 hA = __halves2bfloat162(b0, b1v);
                __nv_bfloat162 hB = __halves2bfloat162(b2v, b3);
                *(ull*)(sm + off) = ((ull)*(uint32_t*)&hB << 32) | *(uint32_t*)&hA;
                __nv_bfloat162 lA = __halves2bfloat162(c0, c1);
                __nv_bfloat162 lB = __halves2bfloat162(c2, c3);
                *(ull*)(sm + off + 16384) = ((ull)*(uint32_t*)&lB << 32) | *(uint32_t*)&lA;
            }
        }

    // ---------------- phase 2: h2pre = h1 @ W2 ----------------
    #pragma unroll
    for (int mf = 0; mf < 2; mf++)
        #pragma unroll
        for (int nf = 0; nf < 8; nf++) {
            acc[mf][nf][0] = 0.f; acc[mf][nf][1] = 0.f;
            acc[mf][nf][2] = 0.f; acc[mf][nf][3] = 0.f;
        }

    #pragma unroll 1
    for (int c = 0; c < 4; c++) {
        cpa_wait0();
        __syncthreads();
        mma_chunk9(acc, sb + H1(c), sb + H1(c) + 16384, sb + W2HI, sb + W2LO,
                   wm * 32, wn * 64, l);
        __syncthreads();
        if (c < 3) {
            #pragma unroll
            for (int i0 = 0; i0 < 4; i0++) {
                int i = i0 * 512 + t;
                cpa16(sb + W2HI + i * 16, g_w2H + (c + 1) * 32768 + i * 16);
                cpa16(sb + W2LO + i * 16, g_w2L + (c + 1) * 32768 + i * 16);
            }
            cpa_commit();
        }
    }

    // ---------------- epilogue: h = relu(acc+b2)+x ; LayerNorm ; out ----------
    float2* sred = (float2*)(sm + LNPART);
    #pragma unroll
    for (int mf = 0; mf < 2; mf++)
        #pragma unroll
        for (int rh = 0; rh < 2; rh++) {
            int r = wm * 32 + mf * 16 + rh * 8 + (l >> 2);
            int gcl = min(rowb + r, NN - 1);
            const float4* xr = (const float4*)(x + (size_t)gcl * DIM);
            float s = 0.f, q = 0.f;
            #pragma unroll
            for (int nq = 0; nq < 4; nq++) {
                int col = wn * 64 + nq * 16 + 4 * j;
                float4 bv = __ldg((const float4*)b2 + (col >> 2));
                float4 xv = __ldg(xr + (col >> 2));
                float h0 = fmaxf(acc[mf][2 * nq][2 * rh]     + bv.x, 0.f) + xv.x;
                float h1 = fmaxf(acc[mf][2 * nq][2 * rh + 1] + bv.y, 0.f) + xv.y;
                float h2 = fmaxf(acc[mf][2 * nq + 1][2 * rh]     + bv.z, 0.f) + xv.z;
                float h3 = fmaxf(acc[mf][2 * nq + 1][2 * rh + 1] + bv.w, 0.f) + xv.w;
                acc[mf][2 * nq][2 * rh]         = h0;
                acc[mf][2 * nq][2 * rh + 1]     = h1;
                acc[mf][2 * nq + 1][2 * rh]     = h2;
                acc[mf][2 * nq + 1][2 * rh + 1] = h3;
                s += (h0 + h1) + (h2 + h3);
                q += h0 * h0 + h1 * h1 + h2 * h2 + h3 * h3;
            }
            s += __shfl_xor_sync(0xffffffffu, s, 1);
            q += __shfl_xor_sync(0xffffffffu, q, 1);
            s += __shfl_xor_sync(0xffffffffu, s, 2);
            q += __shfl_xor_sync(0xffffffffu, q, 2);
            if (j == 0) sred[r * 4 + wn] = make_float2(s, q);
        }
    __syncthreads();

    #pragma unroll
    for (int mf = 0; mf < 2; mf++)
        #pragma unroll
        for (int rh = 0; rh < 2; rh++) {
            int r = wm * 32 + mf * 16 + rh * 8 + (l >> 2);
            int grow = rowb + r;
            float2 p0 = sred[r * 4 + 0], p1 = sred[r * 4 + 1];
            float2 p2 = sred[r * 4 + 2], p3 = sred[r * 4 + 3];
            float s = (p0.x + p1.x) + (p2.x + p3.x);
            float q = (p0.y + p1.y) + (p2.y + p3.y);
            float mu = s * (1.0f / 256.0f);
            float var = q * (1.0f / 256.0f) - mu * mu;
            float inv = rsqrtf(var + 1e-5f);
            if (grow < NN) {
                #pragma unroll
                for (int nq = 0; nq < 4; nq++) {
                    int col = wn * 64 + nq * 16 + 4 * j;
                    float4 gv = __ldg((const float4*)gamma + (col >> 2));
                    float4 tv = __ldg((const float4*)beta + (col >> 2));
                    float4 o;
                    o.x = (acc[mf][2 * nq][2 * rh]         - mu) * inv * gv.x + tv.x;
                    o.y = (acc[mf][2 * nq][2 * rh + 1]     - mu) * inv * gv.y + tv.y;
                    o.z = (acc[mf][2 * nq + 1][2 * rh]     - mu) * inv * gv.z + tv.z;
                    o.w = (acc[mf][2 * nq + 1][2 * rh + 1] - mu) * inv * gv.w + tv.w;
                    ((float4*)(out + (size_t)grow * DIM))[col >> 2] = o;
                }
            }
        }
}

// ---------------------------------------------------------------------------
extern "C" void kernel_launch(void* const* d_in, const int* in_sizes, int n_in,
                              void* d_out, int out_size)
{
    const float* x     = (const float*)d_in[0];
    const int*   eidx  = (const int*)d_in[1];     // int32 (JAX x64 disabled)
    const float* ea    = (const float*)d_in[2];
    const float* We    = (const float*)d_in[3];
    const float* be    = (const float*)d_in[4];
    const float* W1    = (const float*)d_in[5];
    const float* b1    = (const float*)d_in[6];
    const float* W2    = (const float*)d_in[7];
    const float* b2    = (const float*)d_in[8];
    const float* gamma = (const float*)d_in[9];
    const float* beta  = (const float*)d_in[10];
    float* out         = (float*)d_out;

    cudaFuncSetAttribute(k_edge, cudaFuncAttributeMaxDynamicSharedMemorySize, E_SMEM);
    cudaFuncSetAttribute(k_mlp, cudaFuncAttributeMaxDynamicSharedMemorySize, P_SMEM);

    k_zero<<<196, 256>>>();
    k_prep<<<288, 256>>>(We, W1, W2);
    k_init<<<12500, 256>>>((const float4*)x);
    k_hist<<<3125, 256>>>(eidx);
    k_scan<<<1, 1024>>>();
    k_scatter<<<3125, 256>>>(eidx);
    k_edge<<<6250, 256, E_SMEM>>>(x, ea, be);
    k_mlp<<<RB, 512, P_SMEM>>>(x, b1, b2, gamma, beta, out);
}

// round 15
// speedup vs baseline: 2.4404x; 2.4404x over previous
#include <cuda_runtime.h>
#include <cuda_bf16.h>
#include <cstdint>

#define NN 50000
#define NE 800000
#define DIM 256
#define RB 391   // ceil(NN/128)

typedef unsigned long long ull;

// ---------------- global scratch ----------------
__device__ __align__(16) float g_z[NN * DIM];          // z = x + aggr
__device__ __align__(128) char g_weH[32768];           // We image [64k][256n] bf16 hi (swz<9>)
__device__ __align__(128) char g_weL[32768];
__device__ __align__(128) char g_w1H[131072];          // W1 images, 4 chunks x 32KB
__device__ __align__(128) char g_w1L[131072];
__device__ __align__(128) char g_w2H[131072];
__device__ __align__(128) char g_w2L[131072];

// ---------------- helpers ----------------
template <int S>
__device__ __forceinline__ uint32_t swz(uint32_t off) {
    return off ^ (((off >> S) & 7u) << 4);
}
__device__ __forceinline__ int permp(int np) {
    return (np & ~7) | ((np & 7) >> 1) | ((np & 1) << 2);
}
__device__ __forceinline__ uint32_t smem_u32(const void* p) {
    uint32_t a;
    asm("{ .reg .u64 t; cvta.to.shared.u64 t, %1; cvt.u32.u64 %0, t; }" : "=r"(a) : "l"(p));
    return a;
}
__device__ __forceinline__ void ldsm4(uint32_t r[4], uint32_t a) {
    asm volatile("ldmatrix.sync.aligned.m8n8.x4.shared.b16 {%0,%1,%2,%3}, [%4];"
                 : "=r"(r[0]), "=r"(r[1]), "=r"(r[2]), "=r"(r[3]) : "r"(a));
}
__device__ __forceinline__ void ldsm4t(uint32_t r[4], uint32_t a) {
    asm volatile("ldmatrix.sync.aligned.m8n8.x4.trans.shared.b16 {%0,%1,%2,%3}, [%4];"
                 : "=r"(r[0]), "=r"(r[1]), "=r"(r[2]), "=r"(r[3]) : "r"(a));
}
__device__ __forceinline__ void mma16816(float d[4], const uint32_t a[4], const uint32_t b[2]) {
    asm volatile("mma.sync.aligned.m16n8k16.row.col.f32.bf16.bf16.f32 "
                 "{%0,%1,%2,%3}, {%4,%5,%6,%7}, {%8,%9}, {%0,%1,%2,%3};"
                 : "+f"(d[0]), "+f"(d[1]), "+f"(d[2]), "+f"(d[3])
                 : "r"(a[0]), "r"(a[1]), "r"(a[2]), "r"(a[3]), "r"(b[0]), "r"(b[1]));
}
__device__ __forceinline__ void red4(float* a, float4 v) {
    asm volatile("red.global.add.v4.f32 [%0], {%1,%2,%3,%4};"
                 :: "l"(a), "f"(v.x), "f"(v.y), "f"(v.z), "f"(v.w));
}
__device__ __forceinline__ void cpa16(uint32_t dst, const void* src) {
    asm volatile("cp.async.cg.shared.global [%0], [%1], 16;" :: "r"(dst), "l"(src));
}
__device__ __forceinline__ void cpa_commit() { asm volatile("cp.async.commit_group;"); }
__device__ __forceinline__ void cpa_wait0()  { asm volatile("cp.async.wait_group 0;"); }

__device__ __forceinline__ void store_pair(char* bH, char* bL, uint32_t off, float2 v) {
    __nv_bfloat16 h0 = __float2bfloat16(v.x), h1 = __float2bfloat16(v.y);
    __nv_bfloat16 l0 = __float2bfloat16(v.x - __bfloat162float(h0));
    __nv_bfloat16 l1 = __float2bfloat16(v.y - __bfloat162float(h1));
    *(__nv_bfloat162*)(bH + off) = __halves2bfloat162(h0, h1);
    *(__nv_bfloat162*)(bL + off) = __halves2bfloat162(l0, l1);
}
__device__ __forceinline__ void store_hi(char* bH, uint32_t off, float2 v) {
    *(__nv_bfloat162*)(bH + off) =
        __halves2bfloat162(__float2bfloat16(v.x), __float2bfloat16(v.y));
}

// ---------------------------------------------------------------------------
// mma_chunk9: 3-pass (Ah*Bh + Ah*Bl + Al*Bh), B 512B rows swz<9>  (MLPs)
// ---------------------------------------------------------------------------
__device__ __forceinline__ void mma_chunk9(float acc[2][8][4],
    uint32_t aH, uint32_t aL, uint32_t bH, uint32_t bL,
    int mbase, int nbase, int l)
{
    const int lr = l & 7, lg8 = ((l >> 3) & 1) * 8, lh8 = (l >> 4) * 8;
    #pragma unroll
    for (int ks = 0; ks < 4; ks++) {
        uint32_t a[2][4], bh[8][2], bl[8][2];
        #pragma unroll
        for (int mf = 0; mf < 2; mf++)
            ldsm4(a[mf], aH + swz<7>((uint32_t)((mbase + mf * 16 + lr + lg8) * 128
                                                + (ks * 16 + lh8) * 2)));
        #pragma unroll
        for (int nq = 0; nq < 4; nq++) {
            uint32_t r4[4];
            uint32_t off = swz<9>((uint32_t)((ks * 16 + lr + lg8) * 512
                                             + (nbase + nq * 16 + lh8) * 2));
            ldsm4t(r4, bH + off);
            bh[2 * nq][0] = r4[0]; bh[2 * nq][1] = r4[1];
            bh[2 * nq + 1][0] = r4[2]; bh[2 * nq + 1][1] = r4[3];
            ldsm4t(r4, bL + off);
            bl[2 * nq][0] = r4[0]; bl[2 * nq][1] = r4[1];
            bl[2 * nq + 1][0] = r4[2]; bl[2 * nq + 1][1] = r4[3];
        }
        #pragma unroll
        for (int mf = 0; mf < 2; mf++)
            #pragma unroll
            for (int nf = 0; nf < 8; nf++)
                mma16816(acc[mf][nf], a[mf], bh[nf]);
        #pragma unroll
        for (int mf = 0; mf < 2; mf++)
            #pragma unroll
            for (int nf = 0; nf < 8; nf++)
                mma16816(acc[mf][nf], a[mf], bl[nf]);
        #pragma unroll
        for (int mf = 0; mf < 2; mf++)
            ldsm4(a[mf], aL + swz<7>((uint32_t)((mbase + mf * 16 + lr + lg8) * 128
                                                + (ks * 16 + lh8) * 2)));
        #pragma unroll
        for (int mf = 0; mf < 2; mf++)
            #pragma unroll
            for (int nf = 0; nf < 8; nf++)
                mma16816(acc[mf][nf], a[mf], bh[nf]);
    }
}

// ---------------------------------------------------------------------------
// mma_chunk2: 2-pass (Ah*Bh + Ah*Bl) — edge GEMM only. A-residual dropped
// (per-edge data residual averages out across K and the dst aggregation;
// the systematic B/We residual is KEPT via the Bl pass).
// ---------------------------------------------------------------------------
__device__ __forceinline__ void mma_chunk2(float acc[2][8][4],
    uint32_t aH, uint32_t bH, uint32_t bL, int mbase, int nbase, int l)
{
    const int lr = l & 7, lg8 = ((l >> 3) & 1) * 8, lh8 = (l >> 4) * 8;
    #pragma unroll
    for (int ks = 0; ks < 4; ks++) {
        uint32_t a[2][4], bh[8][2], bl[8][2];
        #pragma unroll
        for (int mf = 0; mf < 2; mf++)
            ldsm4(a[mf], aH + swz<7>((uint32_t)((mbase + mf * 16 + lr + lg8) * 128
                                                + (ks * 16 + lh8) * 2)));
        #pragma unroll
        for (int nq = 0; nq < 4; nq++) {
            uint32_t r4[4];
            uint32_t off = swz<9>((uint32_t)((ks * 16 + lr + lg8) * 512
                                             + (nbase + nq * 16 + lh8) * 2));
            ldsm4t(r4, bH + off);
            bh[2 * nq][0] = r4[0]; bh[2 * nq][1] = r4[1];
            bh[2 * nq + 1][0] = r4[2]; bh[2 * nq + 1][1] = r4[3];
            ldsm4t(r4, bL + off);
            bl[2 * nq][0] = r4[0]; bl[2 * nq][1] = r4[1];
            bl[2 * nq + 1][0] = r4[2]; bl[2 * nq + 1][1] = r4[3];
        }
        #pragma unroll
        for (int mf = 0; mf < 2; mf++)
            #pragma unroll
            for (int nf = 0; nf < 8; nf++)
                mma16816(acc[mf][nf], a[mf], bh[nf]);
        #pragma unroll
        for (int mf = 0; mf < 2; mf++)
            #pragma unroll
            for (int nf = 0; nf < 8; nf++)
                mma16816(acc[mf][nf], a[mf], bl[nf]);
    }
}

// ---------------------------------------------------------------------------
// k_prep: build bf16 hi/lo weight images (R11 version)
// ---------------------------------------------------------------------------
__global__ __launch_bounds__(256) void k_prep(const float* __restrict__ We,
                                              const float* __restrict__ W1,
                                              const float* __restrict__ W2)
{
    int i = blockIdx.x * 256 + threadIdx.x;
    if (i < 8192) {
        int k = i >> 7, np = i & 127;
        uint32_t off = swz<9>((uint32_t)(k * 512 + permp(np) * 4));
        store_pair(g_weH, g_weL, off, ((const float2*)We)[i]);
    } else if (i < 40960) {
        int j = i - 8192;
        int kc = j >> 13, k = (j >> 7) & 63, np = j & 127;
        uint32_t off = (uint32_t)(kc * 32768) + swz<9>((uint32_t)(k * 512 + permp(np) * 4));
        store_pair(g_w1H, g_w1L, off, ((const float2*)W1)[j]);
    } else if (i < 73728) {
        int j = i - 40960;
        int kc = j >> 13, k = (j >> 7) & 63, np = j & 127;
        uint32_t off = (uint32_t)(kc * 32768) + swz<9>((uint32_t)(k * 512 + permp(np) * 4));
        store_pair(g_w2H, g_w2L, off, ((const float2*)W2)[j]);
    }
}

// ---------------------------------------------------------------------------
// k_init: z = x
// ---------------------------------------------------------------------------
__global__ __launch_bounds__(256) void k_init(const float4* __restrict__ x) {
    int i = blockIdx.x * 256 + threadIdx.x;
    reinterpret_cast<float4*>(g_z)[i] = x[i];
}

// ---------------------------------------------------------------------------
// k_edge: CTA = 128 edges, 256 threads (wm4 x wn2), N in 2 halves, occ 2.
// msg = relu(ea@We + x[src] + be) -> red.v4 into g_z[dst].
// 2-pass split GEMM (A-hi only). R11 structure otherwise.
// ---------------------------------------------------------------------------
#define E_AH 0
#define E_BH 16384
#define E_BL 49152
#define E_SMEM 81920

__global__ __launch_bounds__(256, 2) void k_edge(
    const float* __restrict__ x, const int* __restrict__ eidx,
    const float* __restrict__ ea, const float* __restrict__ be)
{
    extern __shared__ char sm[];
    const int t = threadIdx.x, w = t >> 5, l = t & 31;
    const int wm = w & 3, wn = w >> 2, j = l & 3;
    const uint32_t sb = smem_u32(sm);

    // B: bulk cp.async of pre-built We images
    #pragma unroll
    for (int i0 = 0; i0 < 8; i0++) {
        int i = i0 * 256 + t;
        cpa16(sb + E_BH + i * 16, g_weH + i * 16);
        cpa16(sb + E_BL + i * 16, g_weL + i * 16);
    }
    cpa_commit();

    // A: convert edge_attr tile [128][64] to bf16 hi (residual dropped)
    const float2* ea2 = (const float2*)(ea + (size_t)blockIdx.x * (128 * 64));
    #pragma unroll
    for (int i0 = 0; i0 < 16; i0++) {
        int i = i0 * 256 + t;
        int r = i >> 5, kp = i & 31;
        store_hi(sm + E_AH, swz<7>((uint32_t)(r * 128 + kp * 4)), ea2[i]);
    }
    cpa_wait0();
    __syncthreads();

    // per-thread edge rows (4): wm*32 + mf*16 + rh*8 + (l>>2);  q = mf*2+rh
    int si[4], di[4];
    #pragma unroll
    for (int q = 0; q < 4; q++) {
        int r = wm * 32 + (q >> 1) * 16 + (q & 1) * 8 + (l >> 2);
        long long e = (long long)blockIdx.x * 128 + r;
        si[q] = eidx[e]; di[q] = eidx[NE + e];
    }

    #pragma unroll 1
    for (int hf = 0; hf < 2; hf++) {
        const int colbase = hf * 128 + wn * 64;
        float4 xv[4], bv[4];
        #pragma unroll
        for (int nq = 0; nq < 4; nq++) {
            int c4 = (colbase + nq * 16 + 4 * j) >> 2;
            xv[nq] = __ldg((const float4*)(x + (size_t)si[0] * DIM) + c4);
            bv[nq] = __ldg((const float4*)be + c4);
        }

        float acc[2][8][4];
        #pragma unroll
        for (int mf = 0; mf < 2; mf++)
            #pragma unroll
            for (int nf = 0; nf < 8; nf++) {
                acc[mf][nf][0] = 0.f; acc[mf][nf][1] = 0.f;
                acc[mf][nf][2] = 0.f; acc[mf][nf][3] = 0.f;
            }
        mma_chunk2(acc, sb + E_AH, sb + E_BH, sb + E_BL, wm * 32, colbase, l);

        #pragma unroll
        for (int q = 0; q < 4; q++) {
            float4 cur[4];
            #pragma unroll
            for (int nq = 0; nq < 4; nq++) cur[nq] = xv[nq];
            if (q < 3) {
                #pragma unroll
                for (int nq = 0; nq < 4; nq++) {
                    int c4 = (colbase + nq * 16 + 4 * j) >> 2;
                    xv[nq] = __ldg((const float4*)(x + (size_t)si[q + 1] * DIM) + c4);
                }
            }
            const int mf = q >> 1, rh = q & 1;
            float* zd = g_z + (size_t)di[q] * DIM;
            #pragma unroll
            for (int nq = 0; nq < 4; nq++) {
                int col = colbase + nq * 16 + 4 * j;
                float4 o;
                o.x = fmaxf(acc[mf][2 * nq][2 * rh]     + cur[nq].x + bv[nq].x, 0.f);
                o.y = fmaxf(acc[mf][2 * nq][2 * rh + 1] + cur[nq].y + bv[nq].y, 0.f);
                o.z = fmaxf(acc[mf][2 * nq + 1][2 * rh]     + cur[nq].z + bv[nq].z, 0.f);
                o.w = fmaxf(acc[mf][2 * nq + 1][2 * rh + 1] + cur[nq].w + bv[nq].w, 0.f);
                red4(zd + col, o);
            }
        }
    }
}

// ---------------------------------------------------------------------------
// k_mlp (FUSED, R11): layer1 -> h1 smem -> layer2 -> LayerNorm -> out
// 512 threads (wm4 x wn4), CTA = 128 rows x 256 cols.
// ---------------------------------------------------------------------------
#define P_A(buf)  ((buf) * 32768)
#define P_AL(buf) ((buf) * 32768 + 16384)
#define P_B(buf)  (65536 + (buf) * 65536)
#define P_BL(buf) (65536 + (buf) * 65536 + 32768)
#define H1(kc)    ((kc) * 32768)
#define W2HI      131072
#define W2LO      163840
#define LNPART    131072
#define P_SMEM    196608

__global__ __launch_bounds__(512, 1) void k_mlp(
    const float* __restrict__ x, const float* __restrict__ b1,
    const float* __restrict__ b2, const float* __restrict__ gamma,
    const float* __restrict__ beta, float* __restrict__ out)
{
    extern __shared__ char sm[];
    const int t = threadIdx.x, w = t >> 5, l = t & 31;
    const int wm = w & 3, wn = w >> 2, j = l & 3;
    const uint32_t sb = smem_u32(sm);
    const int rb = blockIdx.x, rowb = rb * 128;

    // ---------------- phase 1: h1pre = z @ W1 ----------------
    #pragma unroll
    for (int i0 = 0; i0 < 4; i0++) {
        int i = i0 * 512 + t;
        cpa16(sb + P_B(0) + i * 16, g_w1H + i * 16);
        cpa16(sb + P_BL(0) + i * 16, g_w1L + i * 16);
    }
    cpa_commit();
    #pragma unroll
    for (int i0 = 0; i0 < 8; i0++) {
        int i = i0 * 512 + t;
        int r = i >> 5, kp = i & 31;
        int row = min(rowb + r, NN - 1);
        float2 v = *(const float2*)(g_z + (size_t)row * DIM + kp * 2);
        store_pair(sm + P_A(0), sm + P_AL(0), swz<7>((uint32_t)(r * 128 + kp * 4)), v);
    }

    float acc[2][8][4];
    #pragma unroll
    for (int mf = 0; mf < 2; mf++)
        #pragma unroll
        for (int nf = 0; nf < 8; nf++) {
            acc[mf][nf][0] = 0.f; acc[mf][nf][1] = 0.f;
            acc[mf][nf][2] = 0.f; acc[mf][nf][3] = 0.f;
        }

    #pragma unroll 1
    for (int c = 0; c < 4; c++) {
        cpa_wait0();
        __syncthreads();
        if (c < 3) {
            int nb = (c + 1) & 1;
            #pragma unroll
            for (int i0 = 0; i0 < 4; i0++) {
                int i = i0 * 512 + t;
                cpa16(sb + P_B(nb) + i * 16, g_w1H + (c + 1) * 32768 + i * 16);
                cpa16(sb + P_BL(nb) + i * 16, g_w1L + (c + 1) * 32768 + i * 16);
            }
            cpa_commit();
            #pragma unroll
            for (int i0 = 0; i0 < 8; i0++) {
                int i = i0 * 512 + t;
                int r = i >> 5, kp = i & 31;
                int row = min(rowb + r, NN - 1);
                float2 v = *(const float2*)(g_z + (size_t)row * DIM + (c + 1) * 64 + kp * 2);
                store_pair(sm + P_A(nb), sm + P_AL(nb),
                           swz<7>((uint32_t)(r * 128 + kp * 4)), v);
            }
        }
        int cb = c & 1;
        mma_chunk9(acc, sb + P_A(cb), sb + P_AL(cb), sb + P_B(cb), sb + P_BL(cb),
                   wm * 32, wn * 64, l);
    }
    __syncthreads();

    // prefetch W2 chunk 0 (overlaps the h1 conversion)
    #pragma unroll
    for (int i0 = 0; i0 < 4; i0++) {
        int i = i0 * 512 + t;
        cpa16(sb + W2HI + i * 16, g_w2H + i * 16);
        cpa16(sb + W2LO + i * 16, g_w2L + i * 16);
    }
    cpa_commit();

    // h1 = relu(acc + b1) -> bf16 hi/lo images in smem
    #pragma unroll
    for (int mf = 0; mf < 2; mf++)
        #pragma unroll
        for (int rh = 0; rh < 2; rh++) {
            int r = wm * 32 + mf * 16 + rh * 8 + (l >> 2);
            #pragma unroll
            for (int nq = 0; nq < 4; nq++) {
                int col = wn * 64 + nq * 16 + 4 * j;
                float4 bv = __ldg((const float4*)b1 + (col >> 2));
                float h0 = fmaxf(acc[mf][2 * nq][2 * rh]     + bv.x, 0.f);
                float h1 = fmaxf(acc[mf][2 * nq][2 * rh + 1] + bv.y, 0.f);
                float h2 = fmaxf(acc[mf][2 * nq + 1][2 * rh]     + bv.z, 0.f);
                float h3 = fmaxf(acc[mf][2 * nq + 1][2 * rh + 1] + bv.w, 0.f);
                __nv_bfloat16 b0 = __float2bfloat16(h0), b1v = __float2bfloat16(h1);
                __nv_bfloat16 b2v = __float2bfloat16(h2), b3 = __float2bfloat16(h3);
                __nv_bfloat16 c0 = __float2bfloat16(h0 - __bfloat162float(b0));
                __nv_bfloat16 c1 = __float2bfloat16(h1 - __bfloat162float(b1v));
                __nv_bfloat16 c2 = __float2bfloat16(h2 - __bfloat162float(b2v));
                __nv_bfloat16 c3 = __float2bfloat16(h3 - __bfloat162float(b3));
                int kc = col >> 6, kp = col & 63;
                uint32_t off = (uint32_t)H1(kc) + swz<7>((uint32_t)(r * 128 + kp * 2));
                __nv_bfloat162 hA = __halves2bfloat162(b0, b1v);
                __nv_bfloat162 hB = __halves2bfloat162(b2v, b3);
                *(ull*)(sm + off) = ((ull)*(uint32_t*)&hB << 32) | *(uint32_t*)&hA;
                __nv_bfloat162 lA = __halves2bfloat162(c0, c1);
                __nv_bfloat162 lB = __halves2bfloat162(c2, c3);
                *(ull*)(sm + off + 16384) = ((ull)*(uint32_t*)&lB << 32) | *(uint32_t*)&lA;
            }
        }

    // ---------------- phase 2: h2pre = h1 @ W2 ----------------
    #pragma unroll
    for (int mf = 0; mf < 2; mf++)
        #pragma unroll
        for (int nf = 0; nf < 8; nf++) {
            acc[mf][nf][0] = 0.f; acc[mf][nf][1] = 0.f;
            acc[mf][nf][2] = 0.f; acc[mf][nf][3] = 0.f;
        }

    #pragma unroll 1
    for (int c = 0; c < 4; c++) {
        cpa_wait0();
        __syncthreads();
        mma_chunk9(acc, sb + H1(c), sb + H1(c) + 16384, sb + W2HI, sb + W2LO,
                   wm * 32, wn * 64, l);
        __syncthreads();
        if (c < 3) {
            #pragma unroll
            for (int i0 = 0; i0 < 4; i0++) {
                int i = i0 * 512 + t;
                cpa16(sb + W2HI + i * 16, g_w2H + (c + 1) * 32768 + i * 16);
                cpa16(sb + W2LO + i * 16, g_w2L + (c + 1) * 32768 + i * 16);
            }
            cpa_commit();
        }
    }

    // ---------------- epilogue: h = relu(acc+b2)+x ; LayerNorm ; out ----------
    float2* sred = (float2*)(sm + LNPART);
    #pragma unroll
    for (int mf = 0; mf < 2; mf++)
        #pragma unroll
        for (int rh = 0; rh < 2; rh++) {
            int r = wm * 32 + mf * 16 + rh * 8 + (l >> 2);
            int gcl = min(rowb + r, NN - 1);
            const float4* xr = (const float4*)(x + (size_t)gcl * DIM);
            float s = 0.f, q = 0.f;
            #pragma unroll
            for (int nq = 0; nq < 4; nq++) {
                int col = wn * 64 + nq * 16 + 4 * j;
                float4 bv = __ldg((const float4*)b2 + (col >> 2));
                float4 xv = __ldg(xr + (col >> 2));
                float h0 = fmaxf(acc[mf][2 * nq][2 * rh]     + bv.x, 0.f) + xv.x;
                float h1 = fmaxf(acc[mf][2 * nq][2 * rh + 1] + bv.y, 0.f) + xv.y;
                float h2 = fmaxf(acc[mf][2 * nq + 1][2 * rh]     + bv.z, 0.f) + xv.z;
                float h3 = fmaxf(acc[mf][2 * nq + 1][2 * rh + 1] + bv.w, 0.f) + xv.w;
                acc[mf][2 * nq][2 * rh]         = h0;
                acc[mf][2 * nq][2 * rh + 1]     = h1;
                acc[mf][2 * nq + 1][2 * rh]     = h2;
                acc[mf][2 * nq + 1][2 * rh + 1] = h3;
                s += (h0 + h1) + (h2 + h3);
                q += h0 * h0 + h1 * h1 + h2 * h2 + h3 * h3;
            }
            s += __shfl_xor_sync(0xffffffffu, s, 1);
            q += __shfl_xor_sync(0xffffffffu, q, 1);
            s += __shfl_xor_sync(0xffffffffu, s, 2);
            q += __shfl_xor_sync(0xffffffffu, q, 2);
            if (j == 0) sred[r * 4 + wn] = make_float2(s, q);
        }
    __syncthreads();

    #pragma unroll
    for (int mf = 0; mf < 2; mf++)
        #pragma unroll
        for (int rh = 0; rh < 2; rh++) {
            int r = wm * 32 + mf * 16 + rh * 8 + (l >> 2);
            int grow = rowb + r;
            float2 p0 = sred[r * 4 + 0], p1 = sred[r * 4 + 1];
            float2 p2 = sred[r * 4 + 2], p3 = sred[r * 4 + 3];
            float s = (p0.x + p1.x) + (p2.x + p3.x);
            float q = (p0.y + p1.y) + (p2.y + p3.y);
            float mu = s * (1.0f / 256.0f);
            float var = q * (1.0f / 256.0f) - mu * mu;
            float inv = rsqrtf(var + 1e-5f);
            if (grow < NN) {
                #pragma unroll
                for (int nq = 0; nq < 4; nq++) {
                    int col = wn * 64 + nq * 16 + 4 * j;
                    float4 gv = __ldg((const float4*)gamma + (col >> 2));
                    float4 tv = __ldg((const float4*)beta + (col >> 2));
                    float4 o;
                    o.x = (acc[mf][2 * nq][2 * rh]         - mu) * inv * gv.x + tv.x;
                    o.y = (acc[mf][2 * nq][2 * rh + 1]     - mu) * inv * gv.y + tv.y;
                    o.z = (acc[mf][2 * nq + 1][2 * rh]     - mu) * inv * gv.z + tv.z;
                    o.w = (acc[mf][2 * nq + 1][2 * rh + 1] - mu) * inv * gv.w + tv.w;
                    ((float4*)(out + (size_t)grow * DIM))[col >> 2] = o;
                }
            }
        }
}

// ---------------------------------------------------------------------------
extern "C" void kernel_launch(void* const* d_in, const int* in_sizes, int n_in,
                              void* d_out, int out_size)
{
    const float* x     = (const float*)d_in[0];
    const int*   eidx  = (const int*)d_in[1];     // int32 (JAX x64 disabled)
    const float* ea    = (const float*)d_in[2];
    const float* We    = (const float*)d_in[3];
    const float* be    = (const float*)d_in[4];
    const float* W1    = (const float*)d_in[5];
    const float* b1    = (const float*)d_in[6];
    const float* W2    = (const float*)d_in[7];
    const float* b2    = (const float*)d_in[8];
    const float* gamma = (const float*)d_in[9];
    const float* beta  = (const float*)d_in[10];
    float* out         = (float*)d_out;

    cudaFuncSetAttribute(k_edge, cudaFuncAttributeMaxDynamicSharedMemorySize, E_SMEM);
    cudaFuncSetAttribute(k_mlp, cudaFuncAttributeMaxDynamicSharedMemorySize, P_SMEM);

    k_prep<<<288, 256>>>(We, W1, W2);
    k_init<<<12500, 256>>>((const float4*)x);
    k_edge<<<6250, 256, E_SMEM>>>(x, eidx, ea, be);
    k_mlp<<<RB, 512, P_SMEM>>>(x, b1, b2, gamma, beta, out);
}